// round 9
// baseline (speedup 1.0000x reference)
#include <cuda_runtime.h>
#include <cstdint>

// Problem geometry (fixed by setup_inputs: 2048 x 2048 float32).
static constexpr int H = 2048;
static constexpr int W = 2048;
static constexpr int W4 = W / 4;           // float4s per row (512)
static constexpr int NPIX = H * W;
static constexpr int TPB = 256;
static constexpr int NB4 = NPIX / (TPB * 4);  // 4096 blocks for k_colf
static constexpr float FG = 1.0e30f;       // "foreground / out of range" sentinel

// Persistent fused kernel geometry: 512 blocks x 256 threads, 8 float4-tiles
// per thread. __launch_bounds__(256,4) guarantees >=4 blocks/SM co-resident
// -> all 512 blocks resident on 152 SMs -> spin-wait cannot deadlock.
static constexpr int RN_BLOCKS = 512;
static constexpr int RN_TPB = 256;
static constexpr int RN_STRIDE = RN_BLOCKS * RN_TPB;          // 131072 float4s
static constexpr int RN_TILES = NPIX / 4 / RN_STRIDE;         // 8

// Scratch (device globals — no runtime allocation allowed).
__device__ float        g_f[NPIX];            // squared column distance
__device__ unsigned int g_bm[RN_BLOCKS];      // per-block max (float bits)
__device__ volatile float g_scale;            // 255 / max (1.0 if max == 0)
__device__ unsigned int g_count;              // block-completion ticket
__device__ volatile int  g_flag;              // scale-ready flag

__device__ __forceinline__ float4 fg4() { return make_float4(FG, FG, FG, FG); }

// ---------------------------------------------------------------------------
// K1: f = (distance to nearest background along the column)^2.
// One thread = 4 consecutive pixels (one aligned float4). Probes k=1,2 are
// batched (4 independent loads -> MLP); remaining ks run the masked loop.
// Thread 0 also resets the fused kernel's ticket/flag (stream-ordered).
// ---------------------------------------------------------------------------
__global__ void k_colf(const float* __restrict__ img) {
    int t = blockIdx.x * blockDim.x + threadIdx.x;         // float4 index
    if (t == 0) { g_count = 0u; g_flag = 0; }
    int row = (t << 2) >> 11;                              // W == 2048
    const float4* p = reinterpret_cast<const float4*>(img) + t;

    float4 v = __ldg(p);
    float f0 = (v.x <= 0.5f) ? 0.0f : FG;
    float f1 = (v.y <= 0.5f) ? 0.0f : FG;
    float f2 = (v.z <= 0.5f) ? 0.0f : FG;
    float f3 = (v.w <= 0.5f) ? 0.0f : FG;
    unsigned pend = (f0 != 0.0f ? 1u : 0u) | (f1 != 0.0f ? 2u : 0u) |
                    (f2 != 0.0f ? 4u : 0u) | (f3 != 0.0f ? 8u : 0u);
    if (pend) {
        int up = row, down = (H - 1) - row;
        float4 a1 = (up   >= 1) ? __ldg(p - W4)     : fg4();
        float4 b1 = (down >= 1) ? __ldg(p + W4)     : fg4();
        float4 a2 = (up   >= 2) ? __ldg(p - 2 * W4) : fg4();
        float4 b2 = (down >= 2) ? __ldg(p + 2 * W4) : fg4();
        if ((pend & 1u) && (a1.x <= 0.5f || b1.x <= 0.5f)) { f0 = 1.0f; pend &= ~1u; }
        if ((pend & 2u) && (a1.y <= 0.5f || b1.y <= 0.5f)) { f1 = 1.0f; pend &= ~2u; }
        if ((pend & 4u) && (a1.z <= 0.5f || b1.z <= 0.5f)) { f2 = 1.0f; pend &= ~4u; }
        if ((pend & 8u) && (a1.w <= 0.5f || b1.w <= 0.5f)) { f3 = 1.0f; pend &= ~8u; }
        if ((pend & 1u) && (a2.x <= 0.5f || b2.x <= 0.5f)) { f0 = 4.0f; pend &= ~1u; }
        if ((pend & 2u) && (a2.y <= 0.5f || b2.y <= 0.5f)) { f1 = 4.0f; pend &= ~2u; }
        if ((pend & 4u) && (a2.z <= 0.5f || b2.z <= 0.5f)) { f2 = 4.0f; pend &= ~4u; }
        if ((pend & 8u) && (a2.w <= 0.5f || b2.w <= 0.5f)) { f3 = 4.0f; pend &= ~8u; }
        int kcap = max(up, down);
        for (int k = 3; k <= kcap && pend; k++) {
            float4 a = (k <= up)   ? __ldg(p - (size_t)k * W4) : fg4();
            float4 b = (k <= down) ? __ldg(p + (size_t)k * W4) : fg4();
            float fk2 = (float)(k * k);
            if ((pend & 1u) && (a.x <= 0.5f || b.x <= 0.5f)) { f0 = fk2; pend &= ~1u; }
            if ((pend & 2u) && (a.y <= 0.5f || b.y <= 0.5f)) { f1 = fk2; pend &= ~2u; }
            if ((pend & 4u) && (a.z <= 0.5f || b.z <= 0.5f)) { f2 = fk2; pend &= ~4u; }
            if ((pend & 8u) && (a.w <= 0.5f || b.w <= 0.5f)) { f3 = fk2; pend &= ~8u; }
        }
    }
    reinterpret_cast<float4*>(g_f)[t] = make_float4(f0, f1, f2, f3);
}

// ---------------------------------------------------------------------------
// K2 (fused, persistent): row pass + global max + normalize.
// Phase A: per tile (8 strided float4s/thread) run the exact outward row
//   search (12-wide register window covers d<=4; rare tail probes g_f),
//   keep d = sqrt(best) in registers, track running max.
// Phase B: block max -> g_bm; last block reduces 512 maxima -> g_scale, flag.
// Phase C: all blocks spin (thread 0 + syncthreads), then write floor(d*s)
//   straight from registers. No g_d round-trip.
// ---------------------------------------------------------------------------
__global__ void __launch_bounds__(RN_TPB, 4) k_row_norm(float* __restrict__ out) {
    const float4* f4 = reinterpret_cast<const float4*>(g_f);
    float4* op = reinterpret_cast<float4*>(out);
    int base = blockIdx.x * RN_TPB + threadIdx.x;

    float dv[RN_TILES][4];
    float tmax = 0.0f;

#pragma unroll
    for (int it = 0; it < RN_TILES; it++) {
        int t = base + it * RN_STRIDE;
        int px = t << 2;
        int col = px & (W - 1);                            // multiple of 4

        float4 c = __ldg(f4 + t);
        float4 mm = (col >= 4)     ? __ldg(f4 + t - 1) : fg4();
        float4 pp = (col <= W - 8) ? __ldg(f4 + t + 1) : fg4();

        float w[12] = {mm.x, mm.y, mm.z, mm.w, c.x, c.y, c.z, c.w,
                       pp.x, pp.y, pp.z, pp.w};
        float best[4];
#pragma unroll
        for (int l = 0; l < 4; l++) best[l] = w[4 + l];
#pragma unroll
        for (int d = 1; d <= 4; d++) {
            float fd2 = (float)(d * d);
#pragma unroll
            for (int l = 0; l < 4; l++)
                best[l] = fminf(best[l], fminf(w[4 + l - d], w[4 + l + d]) + fd2);
        }
#pragma unroll
        for (int l = 0; l < 4; l++) {
            if (best[l] > 25.0f) {                         // rare tail
                int cl = col + l;
                int maxl = cl, maxr = (W - 1) - cl;
                for (int d = 5; d < W; d++) {
                    float fd2 = (float)(d * d);
                    if (fd2 >= best[l]) break;
                    float lv = (d <= maxl) ? __ldg(&g_f[px + l - d]) : FG;
                    float rv = (d <= maxr) ? __ldg(&g_f[px + l + d]) : FG;
                    best[l] = fminf(best[l], fminf(lv, rv) + fd2);
                }
            }
        }
#pragma unroll
        for (int l = 0; l < 4; l++) {
            float dl = __fsqrt_rn(best[l]);
            dv[it][l] = dl;
            tmax = fmaxf(tmax, dl);
        }
    }

    // ---- Phase B: block max, last-block global reduce ----
    unsigned int ib = __reduce_max_sync(0xffffffffu, __float_as_uint(tmax));
    __shared__ unsigned int sm[RN_TPB / 32];
    __shared__ bool s_last;
    if ((threadIdx.x & 31) == 0) sm[threadIdx.x >> 5] = ib;
    __syncthreads();
    if (threadIdx.x == 0) {
        unsigned int m = sm[0];
#pragma unroll
        for (int wv = 1; wv < RN_TPB / 32; wv++) m = max(m, sm[wv]);
        g_bm[blockIdx.x] = m;
        __threadfence();
        s_last = (atomicAdd(&g_count, 1u) == RN_BLOCKS - 1);
    }
    __syncthreads();

    if (s_last) {
        unsigned int v = 0u;
        for (int i = threadIdx.x; i < RN_BLOCKS; i += RN_TPB)
            v = max(v, g_bm[i]);
        v = __reduce_max_sync(0xffffffffu, v);
        if ((threadIdx.x & 31) == 0) sm[threadIdx.x >> 5] = v;
        __syncthreads();
        if (threadIdx.x == 0) {
            unsigned int m = sm[0];
#pragma unroll
            for (int wv = 1; wv < RN_TPB / 32; wv++) m = max(m, sm[wv]);
            float mx = __uint_as_float(m);
            g_scale = (mx > 0.0f) ? (255.0f / mx) : 1.0f;
            __threadfence();
            g_flag = 1;
        }
    }

    // ---- Phase C: wait for scale, write output from registers ----
    if (threadIdx.x == 0) {
        while (g_flag == 0) { __nanosleep(64); }
    }
    __syncthreads();
    float s = g_scale;                                     // volatile read

#pragma unroll
    for (int it = 0; it < RN_TILES; it++) {
        int t = base + it * RN_STRIDE;
        float4 r;
        r.x = floorf(dv[it][0] * s);
        r.y = floorf(dv[it][1] * s);
        r.z = floorf(dv[it][2] * s);
        r.w = floorf(dv[it][3] * s);
        op[t] = r;
    }
}

extern "C" void kernel_launch(void* const* d_in, const int* in_sizes, int n_in,
                              void* d_out, int out_size) {
    const float* img = (const float*)d_in[0];
    float* out = (float*)d_out;
    (void)in_sizes; (void)n_in; (void)out_size;

    k_colf<<<NB4, TPB>>>(img);
    k_row_norm<<<RN_BLOCKS, RN_TPB>>>(out);
}